// round 7
// baseline (speedup 1.0000x reference)
#include <cuda_runtime.h>

// x: [32, 28, 28, 512] fp32 (only batch 0 used); out: [32, 29, 29, 1] fp32.
#define HH    28
#define WW    28
#define CC    512
#define NPOS  (HH * WW)      // 784
#define OD    29
#define PITCH 33             // odd pitch -> conflict-free column chains
#define OUT2D (OD * OD)      // 841
#define BATCH 32
#define NCTA  49             // 16 warps/CTA * 49 = 784 positions
#define NTHREADS 512

struct __align__(128) PaddedFlag { unsigned int v; unsigned int pad[31]; };

__device__ PaddedFlag   g_flag[NCTA];          // zero-initialized
__device__ __align__(128) unsigned int g_done = 0;
__device__ __align__(128) float g_fsq[NPOS];

__global__ void __launch_bounds__(NTHREADS)
fused_kernel(const float* __restrict__ x, float* __restrict__ out) {
    const int tid  = threadIdx.x;
    const int wid  = tid >> 5;
    const int lane = tid & 31;
    const int p    = blockIdx.x * 16 + wid;    // one warp per spatial position

    __shared__ float I[OD][PITCH];
    __shared__ unsigned int done_s;

    // ---------------- Phase 1: fsq[p] = sum_c x[0,p,c]^2 ----------------
    {
        const float4* xp = reinterpret_cast<const float4*>(x + (size_t)p * CC);
        float s0 = 0.f, s1 = 0.f, s2 = 0.f, s3 = 0.f;   // 4 independent chains
        {
            const float4 a = xp[lane];
            const float4 b = xp[32 + lane];
            const float4 c = xp[64 + lane];
            const float4 d = xp[96 + lane];
            s0 = (a.x * a.x + a.y * a.y) + (a.z * a.z + a.w * a.w);
            s1 = (b.x * b.x + b.y * b.y) + (b.z * b.z + b.w * b.w);
            s2 = (c.x * c.x + c.y * c.y) + (c.z * c.z + c.w * c.w);
            s3 = (d.x * d.x + d.y * d.y) + (d.z * d.z + d.w * d.w);
        }
        float s = (s0 + s1) + (s2 + s3);
        #pragma unroll
        for (int o = 16; o > 0; o >>= 1)
            s += __shfl_xor_sync(0xffffffffu, s, o);
        if (lane == 0)
            g_fsq[p] = s;
    }
    __syncthreads();                           // CTA's 16 g_fsq stores ordered

    // Arrival: release-store this CTA's flag (fence folded into the store).
    if (tid == 0) {
        asm volatile("st.global.release.gpu.u32 [%0], %1;"
                     :: "l"(&g_flag[blockIdx.x].v), "r"(1u) : "memory");
    }
    if (blockIdx.x >= BATCH) return;           // 17 CTAs done

    // ---------------- Phase 2: CTAs 0..31, one batch element each ----------
    // Serial stages confined to warps 0-1 (64 threads, bar.sync 1,64).
    if (wid < 2) {
        if (tid < NCTA) {                      // 49 parallel acquire-polls
            unsigned int v;
            do {
                asm volatile("ld.global.acquire.gpu.u32 %0, [%1];"
                             : "=r"(v) : "l"(&g_flag[tid].v) : "memory");
            } while (v == 0u);
        }
        asm volatile("bar.sync 1, 64;" ::: "memory");   // join: all flags seen

        if (tid == 0)                          // reset election, off detect path
            done_s = atomicAdd(&g_done, 1u);

        // Row cumsums: threads 0-27, straight from L2 (7x float4 per row).
        if (tid < HH) {
            const float4* row = reinterpret_cast<const float4*>(g_fsq + tid * WW);
            float run = 0.f;
            I[tid + 1][0] = 0.f;
            #pragma unroll
            for (int q = 0; q < 7; ++q) {
                const float4 v = __ldcg(&row[q]);
                run += v.x; I[tid + 1][q * 4 + 1] = run;
                run += v.y; I[tid + 1][q * 4 + 2] = run;
                run += v.z; I[tid + 1][q * 4 + 3] = run;
                run += v.w; I[tid + 1][q * 4 + 4] = run;
            }
        }
        if (tid >= 32 && tid < 32 + OD)        // top border row (threads 32-60)
            I[0][tid - 32] = 0.f;
        asm volatile("bar.sync 1, 64;" ::: "memory");

        // Column cumsums: threads 0-27 (stride-33 -> conflict-free).
        if (tid < WW) {
            const int c = tid + 1;
            float run = 0.f;
            #pragma unroll
            for (int r = 1; r <= HH; ++r) {
                run += I[r][c];
                I[r][c] = run;
            }
        }
    }
    __syncthreads();                           // single full-CTA barrier

    // Box sums -> this block's batch slice (2 iterations per thread).
    float* ob = out + (size_t)blockIdx.x * OUT2D;
    #pragma unroll
    for (int k = tid; k < OUT2D; k += NTHREADS) {
        const int i = k / OD, j = k - i * OD;
        const int r0 = min(max(HH / 2 - i, 0), HH);
        const int r1 = min(max(HH / 2 + HH - i, 0), HH);
        const int c0 = min(max(WW / 2 - j, 0), WW);
        const int c1 = min(max(WW / 2 + WW - j, 0), WW);
        ob[k] = I[r1][c1] - I[r0][c1] - I[r1][c0] + I[r0][c0];
    }

    // Last-joined CTA resets flags + counter: safe, every tail CTA already
    // passed its polls before the 32nd election happened.
    if (done_s == (unsigned int)(BATCH - 1)) {
        if (tid < NCTA) g_flag[tid].v = 0u;
        if (tid == 0)   g_done = 0u;
    }
}

extern "C" void kernel_launch(void* const* d_in, const int* in_sizes, int n_in,
                              void* d_out, int out_size) {
    const float* x = (const float*)d_in[0];
    float* out     = (float*)d_out;
    fused_kernel<<<NCTA, NTHREADS>>>(x, out);
}